// round 13
// baseline (speedup 1.0000x reference)
#include <cuda_runtime.h>
#include <cstdint>

#define BB 4
#define SS 4096
#define DD 2048
#define RR 4
#define RFF 16
#define NROWS (BB*SS)   // 16384
#define TRU 8           // rows per block in k_u (2 groups x 4 rows)
#define TRM 16          // rows per block in k_main
#define EPS 1e-6f

typedef unsigned long long u64;

// -------- device scratch (no allocation allowed) --------
__device__ __align__(16) float g_ssq[NROWS];
__device__ __align__(16) float g_u  [RR*NROWS];   // planar [r][row], pre-scaled by rmsnorm
__device__ __align__(16) float g_pu [NROWS*RR];   // row-major
__device__ __align__(16) float g_pw1[NROWS*RFF];  // row-major
__device__ __align__(16) float g_h  [RR*NROWS];   // planar [r][row]
__device__ __align__(16) float g_Vt [RR*DD];      // w*V transposed
__device__ __align__(16) float g_Ut [RR*DD];      // U transposed
__device__ __align__(16) float g_W1t[RFF*DD];     // w*W1 transposed
__device__ float g_G[16];    // U^T U
__device__ float g_M[64];    // U^T (w*W1)
__device__ float g_a[RR];

// -------- packed f32x2 helpers --------
__device__ __forceinline__ u64 fma2(u64 a, u64 b, u64 c){
    u64 d; asm("fma.rn.f32x2 %0, %1, %2, %3;" : "=l"(d) : "l"(a), "l"(b), "l"(c)); return d;
}
__device__ __forceinline__ u64 add2(u64 a, u64 b){
    u64 d; asm("add.rn.f32x2 %0, %1, %2;" : "=l"(d) : "l"(a), "l"(b)); return d;
}
__device__ __forceinline__ u64 pack2(float x, float y){
    u64 r; asm("mov.b64 %0, {%1, %2};" : "=l"(r) : "f"(x), "f"(y)); return r;
}
__device__ __forceinline__ float2 unpack2(u64 p){
    float2 f; asm("mov.b64 {%0, %1}, %2;" : "=f"(f.x), "=f"(f.y) : "l"(p)); return f;
}
__device__ __forceinline__ float warp_sum(float v){
    v += __shfl_down_sync(0xffffffffu, v, 16);
    v += __shfl_down_sync(0xffffffffu, v, 8);
    v += __shfl_down_sync(0xffffffffu, v, 4);
    v += __shfl_down_sync(0xffffffffu, v, 2);
    v += __shfl_down_sync(0xffffffffu, v, 1);
    return v;
}
// butterfly reduce-scatter: after call, each lane holds warp-total of
// value index (lane & (N-1)). N power of 2.
template<int N>
__device__ __forceinline__ float rs_reduce(float (&v)[N], int lane){
    #pragma unroll
    for (int s = N/2; s >= 1; s >>= 1){
        bool up = (lane & s) != 0;
        #pragma unroll
        for (int i = 0; i < s; i++){
            float send = up ? v[i] : v[i+s];
            float keep = up ? v[i+s] : v[i];
            v[i] = keep + __shfl_xor_sync(0xffffffffu, send, s);
        }
    }
    float r = v[0];
    #pragma unroll
    for (int s = N; s < 32; s <<= 1)
        r += __shfl_xor_sync(0xffffffffu, r, s);
    return r;
}
__device__ __forceinline__ float gelu_tanh(float x){
    float c = 0.7978845608028654f * (x + 0.044715f * x * x * x);
    return 0.5f * x * (1.0f + tanhf(c));
}

// ======================= prep (fused): transpose/fold + G/M dots =======================
__global__ void k_prep_all(const float* __restrict__ norm_w, const float* __restrict__ V,
                           const float* __restrict__ U, const float* __restrict__ a_logit,
                           const float* __restrict__ W1){
    int tid = threadIdx.x;
    if (blockIdx.x < 8){
        int d = blockIdx.x * 256 + tid;
        float w = norm_w[d];
        #pragma unroll
        for (int r = 0; r < RR; r++){
            g_Vt[r*DD + d] = w * V[d*RR + r];
            g_Ut[r*DD + d] = U[d*RR + r];
        }
        #pragma unroll
        for (int r = 0; r < RFF; r++)
            g_W1t[r*DD + d] = w * W1[d*RFF + r];
        if (blockIdx.x == 0 && tid < RR) g_a[tid] = 1.0f / (1.0f + expf(-a_logit[tid]));
    } else {
        int j = blockIdx.x - 8;   // 0..79
        float s = 0.f;
        if (j < 16){
            int k = j >> 2, q = j & 3;
            for (int d = tid; d < DD; d += 256)
                s += U[d*RR + k] * U[d*RR + q];
        } else {
            int k = (j-16) >> 4, r = (j-16) & 15;
            for (int d = tid; d < DD; d += 256)
                s += U[d*RR + k] * norm_w[d] * W1[d*RFF + r];
        }
        s = warp_sum(s);
        __shared__ float sh[8];
        if ((tid & 31) == 0) sh[tid >> 5] = s;
        __syncthreads();
        if (tid == 0){
            float t = 0.f;
            #pragma unroll
            for (int i = 0; i < 8; i++) t += sh[i];
            if (j < 16) g_G[j] = t; else g_M[j-16] = t;
        }
    }
}

// ======================= k_u: 8 d's per thread, 2 row-groups (R12 exact) =======================
__global__ void __launch_bounds__(512) k_u(const float* __restrict__ x){
    const int tid = threadIdx.x;
    const int g   = tid >> 8;          // group 0/1
    const int gt  = tid & 255;         // thread within group
    const int w8  = gt >> 5;           // warp within group (0..7)
    const int l   = gt & 31;
    const int rowg = blockIdx.x * TRU + g*4;   // first row of this group

    __shared__ float sred[TRU][25][9];
    __shared__ float tot[TRU][25];

    ulonglong2 xp[4][2];
    #pragma unroll
    for (int i = 0; i < 4; i++){
        const ulonglong2* xr = reinterpret_cast<const ulonglong2*>(x)
                             + (size_t)(rowg+i)*(DD/4) + gt*2;
        xp[i][0] = xr[0];
        xp[i][1] = xr[1];
    }

    // ---- pass 0: ssq + V0..3 ----
    {
        ulonglong2 wp[4][2];
        #pragma unroll
        for (int j = 0; j < 4; j++){
            wp[j][0] = reinterpret_cast<const ulonglong2*>(g_Vt)[j*(DD/4) + gt*2];
            wp[j][1] = reinterpret_cast<const ulonglong2*>(g_Vt)[j*(DD/4) + gt*2 + 1];
        }
        #pragma unroll
        for (int i = 0; i < 4; i++){
            u64 s = fma2(xp[i][0].x, xp[i][0].x,
                    fma2(xp[i][0].y, xp[i][0].y,
                    fma2(xp[i][1].x, xp[i][1].x,
                    fma2(xp[i][1].y, xp[i][1].y, 0ull))));
            float2 fs = unpack2(s);
            float ss = warp_sum(fs.x + fs.y);
            float p[4];
            #pragma unroll
            for (int j = 0; j < 4; j++){
                u64 a = fma2(xp[i][0].x, wp[j][0].x,
                        fma2(xp[i][0].y, wp[j][0].y,
                        fma2(xp[i][1].x, wp[j][1].x,
                        fma2(xp[i][1].y, wp[j][1].y, 0ull))));
                float2 f = unpack2(a);
                p[j] = f.x + f.y;
            }
            float rv = rs_reduce<4>(p, l);
            int ri = g*4 + i;
            if (l == 0) sred[ri][0][w8] = ss;
            if (l < 4)  sred[ri][1+l][w8] = rv;
        }
    }
    __syncthreads();

    // ---- passes 1..5: U (slots 5..8) and W1 quads (slots 9..24) ----
    #pragma unroll
    for (int pass = 1; pass < 6; pass++){
        const float* wsrc = (pass == 1) ? g_Ut : (g_W1t + (pass-2)*4*DD);
        const int slot0   = (pass == 1) ? 5 : (9 + (pass-2)*4);
        ulonglong2 wp[4][2];
        #pragma unroll
        for (int j = 0; j < 4; j++){
            wp[j][0] = reinterpret_cast<const ulonglong2*>(wsrc)[j*(DD/4) + gt*2];
            wp[j][1] = reinterpret_cast<const ulonglong2*>(wsrc)[j*(DD/4) + gt*2 + 1];
        }
        #pragma unroll
        for (int i = 0; i < 4; i++){
            float p[4];
            #pragma unroll
            for (int j = 0; j < 4; j++){
                u64 a = fma2(xp[i][0].x, wp[j][0].x,
                        fma2(xp[i][0].y, wp[j][0].y,
                        fma2(xp[i][1].x, wp[j][1].x,
                        fma2(xp[i][1].y, wp[j][1].y, 0ull))));
                float2 f = unpack2(a);
                p[j] = f.x + f.y;
            }
            float rv = rs_reduce<4>(p, l);
            int ri = g*4 + i;
            if (l < 4) sred[ri][slot0+l][w8] = rv;
        }
        __syncthreads();
    }

    if (tid < TRU*25){
        int row = tid / 25, val = tid % 25;
        float s = 0.f;
        #pragma unroll
        for (int ww = 0; ww < 8; ww++) s += sred[row][val][ww];
        tot[row][val] = s;
    }
    __syncthreads();
    if (tid < TRU*25){
        int row = tid / 25, val = tid % 25;
        int gr = blockIdx.x * TRU + row;
        float s = tot[row][val];
        if (val == 0) g_ssq[gr] = s;
        else if (val < 5){
            float scale = rsqrtf(tot[row][0] * (1.0f/DD) + EPS);
            g_u[(val-1)*NROWS + gr] = scale * s;
        }
        else if (val < 9) g_pu[(size_t)gr*RR + (val-5)] = s;
        else              g_pw1[(size_t)gr*RFF + (val-9)] = s;
    }
}

// ======================= k_scan: warp-parallel linear-recurrence scan =======================
__global__ void __launch_bounds__(256) k_scan(){
    const int b = blockIdx.x >> 2;
    const int r = blockIdx.x & 3;
    const float a = g_a[r];
    const int tid = threadIdx.x, l = tid & 31, w = tid >> 5;
    const float* u = g_u + r*NROWS + b*SS;

    float uu[16];
    float4* uu4 = reinterpret_cast<float4*>(uu);
    #pragma unroll
    for (int i = 0; i < 4; i++)
        uu4[i] = reinterpret_cast<const float4*>(u)[tid*4 + i];

    float f = 0.f;
    #pragma unroll
    for (int i = 0; i < 16; i++) f = a*f + uu[i];

    float A = a; A *= A; A *= A; A *= A; A *= A;   // a^16

    float I = f, As = A;
    #pragma unroll
    for (int st = 0; st < 5; st++){
        float gg = __shfl_up_sync(0xffffffffu, I, 1 << st);
        if (l >= (1 << st)) I += As * gg;
        As *= As;
    }

    __shared__ float Tw[8], Ww[8];
    if (l == 31) Tw[w] = I;
    __syncthreads();
    if (tid == 0){
        float A32 = A;
        #pragma unroll
        for (int k = 0; k < 5; k++) A32 *= A32;  // a^512
        float c = 0.f;
        #pragma unroll
        for (int j = 0; j < 8; j++){ Ww[j] = c; c = A32*c + Tw[j]; }
    }
    __syncthreads();

    float Al = 1.f, p = A;
    #pragma unroll
    for (int bit = 0; bit < 5; bit++){ if ((l >> bit) & 1) Al *= p; p *= p; }
    float Iprev = __shfl_up_sync(0xffffffffu, I, 1);
    float c = ((l == 0) ? 0.f : Iprev) + Al * Ww[w];

    float* hh = g_h + r*NROWS + b*SS;
    float h = c;
    float ho[16];
    #pragma unroll
    for (int i = 0; i < 16; i++){ h = a*h + uu[i]; ho[i] = h; }
    float4* ho4 = reinterpret_cast<float4*>(ho);
    #pragma unroll
    for (int i = 0; i < 4; i++)
        reinterpret_cast<float4*>(hh)[tid*4 + i] = ho4[i];
}

// ======================= k_main (k_post merged in): out = x + U h + g @ W2 =======================
// 256 threads, 2 CTA/SM; thread owns one ulonglong2 (4 floats); 16 rows/block.
// grid = (NROWS/TRM, 2). Phase A computes scale+gelu (was k_post); pre-packed
// scalar table; loop has no pack2.
__global__ void __launch_bounds__(256, 2) k_main(const float* __restrict__ x,
                                                 const float* __restrict__ W2,
                                                 float* __restrict__ out){
    const int row0 = blockIdx.x * TRM;
    const int tid  = threadIdx.x;
    const int q    = blockIdx.y * 256 + tid;   // ulonglong2 index within row (0..511)

    ulonglong2 ut[4], w2[16];
    #pragma unroll
    for (int k = 0; k < 4; k++)
        ut[k] = reinterpret_cast<const ulonglong2*>(g_Ut)[k*(DD/4) + q];
    #pragma unroll
    for (int r = 0; r < RFF; r++)
        w2[r] = reinterpret_cast<const ulonglong2*>(W2)[r*(DD/4) + q];

    __shared__ float sG[16], sM[64], sscale[TRM];
    __shared__ float hsc[TRM][4];
    __shared__ __align__(16) u64 hs2[TRM][20];   // [h0..h3, g0..g15] dup-packed

    // ---- phase A0: load h, G, M ----
    if (tid < TRM*4){
        int row = tid >> 2, k = tid & 3;
        float hv = g_h[k*NROWS + row0 + row];
        hsc[row][k] = hv;
        hs2[row][k] = pack2(hv, hv);
    }
    if (tid >= 128 && tid < 144) sG[tid-128] = g_G[tid-128];
    if (tid >= 160 && tid < 224) sM[tid-160] = g_M[tid-160];
    __syncthreads();

    // ---- phase A1: per-row rmsnorm scale of x1 (one thread per row) ----
    if (tid < TRM){
        int row = tid, gr = row0 + row;
        float s1 = g_ssq[gr];
        float h0 = hsc[row][0], h1 = hsc[row][1], h2 = hsc[row][2], h3 = hsc[row][3];
        float4 p4 = reinterpret_cast<const float4*>(g_pu)[gr];
        s1 += 2.0f*(h0*p4.x + h1*p4.y + h2*p4.z + h3*p4.w);
        float hh[4] = {h0, h1, h2, h3};
        #pragma unroll
        for (int k = 0; k < 4; k++)
            #pragma unroll
            for (int qq = 0; qq < 4; qq++) s1 += hh[k]*hh[qq]*sG[k*4+qq];
        sscale[row] = rsqrtf(s1 * (1.0f/DD) + EPS);
    }
    __syncthreads();

    // ---- phase A2: gelu per (row, r) — 256 threads = 16x16 ----
    {
        int row = tid >> 4, r = tid & 15;
        int gr = row0 + row;
        float t = g_pw1[(size_t)gr*RFF + r];
        #pragma unroll
        for (int k = 0; k < 4; k++) t += hsc[row][k] * sM[k*16 + r];
        float gv = gelu_tanh(t * sscale[row]);
        hs2[row][4+r] = pack2(gv, gv);
    }
    __syncthreads();

    // ---- phase B: streaming loop ----
    const ulonglong2* xr = reinterpret_cast<const ulonglong2*>(x) + (size_t)row0*(DD/4) + q;
    ulonglong2*       op = reinterpret_cast<ulonglong2*>(out)     + (size_t)row0*(DD/4) + q;

    ulonglong2 xa = xr[0];
    #pragma unroll
    for (int row = 0; row < TRM; row++){
        ulonglong2 xn = xa;
        if (row + 1 < TRM) xn = xr[(size_t)(row+1)*(DD/4)];

        u64 a0 = xa.x, a1 = xa.y, b0 = 0ull, b1 = 0ull;
        const ulonglong2* s2 = reinterpret_cast<const ulonglong2*>(&hs2[row][0]);
        #pragma unroll
        for (int i = 0; i < 10; i++){
            ulonglong2 sp = s2[i];           // two dup-packed scalars (LDS.128 broadcast)
            const int j0 = 2*i, j1 = 2*i + 1;
            u64 w0x = (j0 < 4) ? ut[j0].x : w2[j0-4].x;
            u64 w0y = (j0 < 4) ? ut[j0].y : w2[j0-4].y;
            u64 w1x = (j1 < 4) ? ut[j1].x : w2[j1-4].x;
            u64 w1y = (j1 < 4) ? ut[j1].y : w2[j1-4].y;
            a0 = fma2(sp.x, w0x, a0);  a1 = fma2(sp.x, w0y, a1);
            b0 = fma2(sp.y, w1x, b0);  b1 = fma2(sp.y, w1y, b1);
        }
        ulonglong2 o;
        o.x = add2(a0, b0);
        o.y = add2(a1, b1);
        op[(size_t)row*(DD/4)] = o;
        xa = xn;
    }
}

// ======================= launch =======================
extern "C" void kernel_launch(void* const* d_in, const int* in_sizes, int n_in,
                              void* d_out, int out_size){
    const float* x       = (const float*)d_in[0];
    const float* norm_w  = (const float*)d_in[1];
    const float* V       = (const float*)d_in[2];
    const float* U       = (const float*)d_in[3];
    const float* a_logit = (const float*)d_in[4];
    const float* W1      = (const float*)d_in[5];
    const float* W2      = (const float*)d_in[6];
    float* out = (float*)d_out;

    k_prep_all<<<88, 256>>>(norm_w, V, U, a_logit, W1);
    k_u    <<<NROWS/TRU, 512>>>(x);
    k_scan <<<BB*RR, 256>>>();
    dim3 gm(NROWS/TRM, 2);
    k_main <<<gm, 256>>>(x, W2, out);
}

// round 14
// speedup vs baseline: 1.0135x; 1.0135x over previous
#include <cuda_runtime.h>
#include <cstdint>

#define BB 4
#define SS 4096
#define DD 2048
#define RR 4
#define RFF 16
#define NROWS (BB*SS)   // 16384
#define TRU 8           // rows per block in k_u (2 groups x 4 rows)
#define TRM 16          // rows per block in k_main
#define EPS 1e-6f

typedef unsigned long long u64;

// -------- device scratch (no allocation allowed) --------
__device__ __align__(16) float g_ssq[NROWS];
__device__ __align__(16) float g_u  [RR*NROWS];   // planar [r][row], pre-scaled by rmsnorm
__device__ __align__(16) float g_pu [NROWS*RR];   // row-major
__device__ __align__(16) float g_pw1[NROWS*RFF];  // row-major
__device__ __align__(16) float g_h  [RR*NROWS];   // planar [r][row]
__device__ __align__(16) float g_g  [NROWS*RFF];  // row-major
__device__ __align__(16) float g_Vt [RR*DD];      // w*V transposed
__device__ __align__(16) float g_Ut [RR*DD];      // U transposed
__device__ __align__(16) float g_W1t[RFF*DD];     // w*W1 transposed
__device__ float g_G[16];    // U^T U
__device__ float g_M[64];    // U^T (w*W1)
__device__ float g_a[RR];

// -------- packed f32x2 helpers --------
__device__ __forceinline__ u64 fma2(u64 a, u64 b, u64 c){
    u64 d; asm("fma.rn.f32x2 %0, %1, %2, %3;" : "=l"(d) : "l"(a), "l"(b), "l"(c)); return d;
}
__device__ __forceinline__ u64 add2(u64 a, u64 b){
    u64 d; asm("add.rn.f32x2 %0, %1, %2;" : "=l"(d) : "l"(a), "l"(b)); return d;
}
__device__ __forceinline__ u64 pack2(float x, float y){
    u64 r; asm("mov.b64 %0, {%1, %2};" : "=l"(r) : "f"(x), "f"(y)); return r;
}
__device__ __forceinline__ float2 unpack2(u64 p){
    float2 f; asm("mov.b64 {%0, %1}, %2;" : "=f"(f.x), "=f"(f.y) : "l"(p)); return f;
}
__device__ __forceinline__ float warp_sum(float v){
    v += __shfl_down_sync(0xffffffffu, v, 16);
    v += __shfl_down_sync(0xffffffffu, v, 8);
    v += __shfl_down_sync(0xffffffffu, v, 4);
    v += __shfl_down_sync(0xffffffffu, v, 2);
    v += __shfl_down_sync(0xffffffffu, v, 1);
    return v;
}
template<int N>
__device__ __forceinline__ float rs_reduce(float (&v)[N], int lane){
    #pragma unroll
    for (int s = N/2; s >= 1; s >>= 1){
        bool up = (lane & s) != 0;
        #pragma unroll
        for (int i = 0; i < s; i++){
            float send = up ? v[i] : v[i+s];
            float keep = up ? v[i+s] : v[i];
            v[i] = keep + __shfl_xor_sync(0xffffffffu, send, s);
        }
    }
    float r = v[0];
    #pragma unroll
    for (int s = N; s < 32; s <<= 1)
        r += __shfl_xor_sync(0xffffffffu, r, s);
    return r;
}
__device__ __forceinline__ float gelu_tanh(float x){
    float c = 0.7978845608028654f * (x + 0.044715f * x * x * x);
    return 0.5f * x * (1.0f + tanhf(c));
}
// cp.async helpers (16B per thread)
__device__ __forceinline__ void cp_async16(void* saddr, const void* gaddr){
    uint32_t s = (uint32_t)__cvta_generic_to_shared(saddr);
    asm volatile("cp.async.ca.shared.global [%0], [%1], 16;" :: "r"(s), "l"(gaddr));
}
__device__ __forceinline__ void cp_commit(){ asm volatile("cp.async.commit_group;"); }
__device__ __forceinline__ void cp_wait3(){ asm volatile("cp.async.wait_group 3;"); }

// ======================= prep kernels (split for profiler positioning) =======================
__global__ void k_prep_a(const float* __restrict__ a_logit){
    int tid = threadIdx.x;
    if (tid < RR) g_a[tid] = 1.0f / (1.0f + expf(-a_logit[tid]));
}

__global__ void k_prep_fold(const float* __restrict__ norm_w, const float* __restrict__ V,
                            const float* __restrict__ U, const float* __restrict__ W1){
    int d = blockIdx.x * 256 + threadIdx.x;
    float w = norm_w[d];
    #pragma unroll
    for (int r = 0; r < RR; r++){
        g_Vt[r*DD + d] = w * V[d*RR + r];
        g_Ut[r*DD + d] = U[d*RR + r];
    }
    #pragma unroll
    for (int r = 0; r < RFF; r++)
        g_W1t[r*DD + d] = w * W1[d*RFF + r];
}

__global__ void k_prep_gm(const float* __restrict__ norm_w, const float* __restrict__ U,
                          const float* __restrict__ W1){
    int j = blockIdx.x;   // 0..79
    int tid = threadIdx.x;
    float s = 0.f;
    if (j < 16){
        int k = j >> 2, q = j & 3;
        for (int d = tid; d < DD; d += 256)
            s += U[d*RR + k] * U[d*RR + q];
    } else {
        int k = (j-16) >> 4, r = (j-16) & 15;
        for (int d = tid; d < DD; d += 256)
            s += U[d*RR + k] * norm_w[d] * W1[d*RFF + r];
    }
    s = warp_sum(s);
    __shared__ float sh[8];
    if ((tid & 31) == 0) sh[tid >> 5] = s;
    __syncthreads();
    if (tid == 0){
        float t = 0.f;
        #pragma unroll
        for (int i = 0; i < 8; i++) t += sh[i];
        if (j < 16) g_G[j] = t; else g_M[j-16] = t;
    }
}

// ======================= k_u: 8 d's per thread, 2 row-groups (R12 exact) =======================
__global__ void __launch_bounds__(512) k_u(const float* __restrict__ x){
    const int tid = threadIdx.x;
    const int g   = tid >> 8;          // group 0/1
    const int gt  = tid & 255;         // thread within group
    const int w8  = gt >> 5;           // warp within group (0..7)
    const int l   = gt & 31;
    const int rowg = blockIdx.x * TRU + g*4;

    __shared__ float sred[TRU][25][9];
    __shared__ float tot[TRU][25];

    ulonglong2 xp[4][2];
    #pragma unroll
    for (int i = 0; i < 4; i++){
        const ulonglong2* xr = reinterpret_cast<const ulonglong2*>(x)
                             + (size_t)(rowg+i)*(DD/4) + gt*2;
        xp[i][0] = xr[0];
        xp[i][1] = xr[1];
    }

    // ---- pass 0: ssq + V0..3 ----
    {
        ulonglong2 wp[4][2];
        #pragma unroll
        for (int j = 0; j < 4; j++){
            wp[j][0] = reinterpret_cast<const ulonglong2*>(g_Vt)[j*(DD/4) + gt*2];
            wp[j][1] = reinterpret_cast<const ulonglong2*>(g_Vt)[j*(DD/4) + gt*2 + 1];
        }
        #pragma unroll
        for (int i = 0; i < 4; i++){
            u64 s = fma2(xp[i][0].x, xp[i][0].x,
                    fma2(xp[i][0].y, xp[i][0].y,
                    fma2(xp[i][1].x, xp[i][1].x,
                    fma2(xp[i][1].y, xp[i][1].y, 0ull))));
            float2 fs = unpack2(s);
            float ss = warp_sum(fs.x + fs.y);
            float p[4];
            #pragma unroll
            for (int j = 0; j < 4; j++){
                u64 a = fma2(xp[i][0].x, wp[j][0].x,
                        fma2(xp[i][0].y, wp[j][0].y,
                        fma2(xp[i][1].x, wp[j][1].x,
                        fma2(xp[i][1].y, wp[j][1].y, 0ull))));
                float2 f = unpack2(a);
                p[j] = f.x + f.y;
            }
            float rv = rs_reduce<4>(p, l);
            int ri = g*4 + i;
            if (l == 0) sred[ri][0][w8] = ss;
            if (l < 4)  sred[ri][1+l][w8] = rv;
        }
    }
    __syncthreads();

    // ---- passes 1..5: U (slots 5..8) and W1 quads (slots 9..24) ----
    #pragma unroll
    for (int pass = 1; pass < 6; pass++){
        const float* wsrc = (pass == 1) ? g_Ut : (g_W1t + (pass-2)*4*DD);
        const int slot0   = (pass == 1) ? 5 : (9 + (pass-2)*4);
        ulonglong2 wp[4][2];
        #pragma unroll
        for (int j = 0; j < 4; j++){
            wp[j][0] = reinterpret_cast<const ulonglong2*>(wsrc)[j*(DD/4) + gt*2];
            wp[j][1] = reinterpret_cast<const ulonglong2*>(wsrc)[j*(DD/4) + gt*2 + 1];
        }
        #pragma unroll
        for (int i = 0; i < 4; i++){
            float p[4];
            #pragma unroll
            for (int j = 0; j < 4; j++){
                u64 a = fma2(xp[i][0].x, wp[j][0].x,
                        fma2(xp[i][0].y, wp[j][0].y,
                        fma2(xp[i][1].x, wp[j][1].x,
                        fma2(xp[i][1].y, wp[j][1].y, 0ull))));
                float2 f = unpack2(a);
                p[j] = f.x + f.y;
            }
            float rv = rs_reduce<4>(p, l);
            int ri = g*4 + i;
            if (l < 4) sred[ri][slot0+l][w8] = rv;
        }
        __syncthreads();
    }

    if (tid < TRU*25){
        int row = tid / 25, val = tid % 25;
        float s = 0.f;
        #pragma unroll
        for (int ww = 0; ww < 8; ww++) s += sred[row][val][ww];
        tot[row][val] = s;
    }
    __syncthreads();
    if (tid < TRU*25){
        int row = tid / 25, val = tid % 25;
        int gr = blockIdx.x * TRU + row;
        float s = tot[row][val];
        if (val == 0) g_ssq[gr] = s;
        else if (val < 5){
            float scale = rsqrtf(tot[row][0] * (1.0f/DD) + EPS);
            g_u[(val-1)*NROWS + gr] = scale * s;
        }
        else if (val < 9) g_pu[(size_t)gr*RR + (val-5)] = s;
        else              g_pw1[(size_t)gr*RFF + (val-9)] = s;
    }
}

// ======================= k_scan: warp-parallel linear-recurrence scan =======================
__global__ void __launch_bounds__(256) k_scan(){
    const int b = blockIdx.x >> 2;
    const int r = blockIdx.x & 3;
    const float a = g_a[r];
    const int tid = threadIdx.x, l = tid & 31, w = tid >> 5;
    const float* u = g_u + r*NROWS + b*SS;

    float uu[16];
    float4* uu4 = reinterpret_cast<float4*>(uu);
    #pragma unroll
    for (int i = 0; i < 4; i++)
        uu4[i] = reinterpret_cast<const float4*>(u)[tid*4 + i];

    float f = 0.f;
    #pragma unroll
    for (int i = 0; i < 16; i++) f = a*f + uu[i];

    float A = a; A *= A; A *= A; A *= A; A *= A;   // a^16

    float I = f, As = A;
    #pragma unroll
    for (int st = 0; st < 5; st++){
        float gg = __shfl_up_sync(0xffffffffu, I, 1 << st);
        if (l >= (1 << st)) I += As * gg;
        As *= As;
    }

    __shared__ float Tw[8], Ww[8];
    if (l == 31) Tw[w] = I;
    __syncthreads();
    if (tid == 0){
        float A32 = A;
        #pragma unroll
        for (int k = 0; k < 5; k++) A32 *= A32;  // a^512
        float c = 0.f;
        #pragma unroll
        for (int j = 0; j < 8; j++){ Ww[j] = c; c = A32*c + Tw[j]; }
    }
    __syncthreads();

    float Al = 1.f, p = A;
    #pragma unroll
    for (int bit = 0; bit < 5; bit++){ if ((l >> bit) & 1) Al *= p; p *= p; }
    float Iprev = __shfl_up_sync(0xffffffffu, I, 1);
    float c = ((l == 0) ? 0.f : Iprev) + Al * Ww[w];

    float* hh = g_h + r*NROWS + b*SS;
    float h = c;
    float ho[16];
    #pragma unroll
    for (int i = 0; i < 16; i++){ h = a*h + uu[i]; ho[i] = h; }
    float4* ho4 = reinterpret_cast<float4*>(ho);
    #pragma unroll
    for (int i = 0; i < 4; i++)
        reinterpret_cast<float4*>(hh)[tid*4 + i] = ho4[i];
}

// ======================= k_post: per-row scale1, t, gelu (R12 exact) =======================
__global__ void __launch_bounds__(256) k_post(){
    __shared__ float sG[16], sM[64];
    int tid = threadIdx.x;
    if (tid < 16) sG[tid] = g_G[tid];
    if (tid < 64) sM[tid] = g_M[tid];
    __syncthreads();

    int row = blockIdx.x * 256 + tid;
    float h[4], p[4];
    #pragma unroll
    for (int k = 0; k < 4; k++) h[k] = g_h[k*NROWS + row];
    float4 p4 = reinterpret_cast<const float4*>(g_pu)[row];
    p[0]=p4.x; p[1]=p4.y; p[2]=p4.z; p[3]=p4.w;

    float s1 = g_ssq[row];
    #pragma unroll
    for (int k = 0; k < 4; k++) s1 += 2.0f * h[k] * p[k];
    #pragma unroll
    for (int k = 0; k < 4; k++)
        #pragma unroll
        for (int q = 0; q < 4; q++) s1 += h[k] * h[q] * sG[k*4+q];
    float scale = rsqrtf(s1 * (1.0f/DD) + EPS);

    #pragma unroll
    for (int r = 0; r < RFF; r++){
        float t = g_pw1[(size_t)row*RFF + r];
        #pragma unroll
        for (int k = 0; k < 4; k++) t += h[k] * sM[k*16 + r];
        g_g[(size_t)row*RFF + r] = gelu_tanh(t * scale);
    }
}

// ======================= k_main: out = x + U h + g @ W2 (cp.async depth-4 ring) =======================
// 256 threads, 2 CTA/SM; thread owns one ulonglong2 (4 floats); 16 rows/block.
// grid = (NROWS/TRM, 2)
__global__ void __launch_bounds__(256, 2) k_main(const float* __restrict__ x,
                                                 const float* __restrict__ W2,
                                                 float* __restrict__ out){
    const int row0 = blockIdx.x * TRM;
    const int tid  = threadIdx.x;
    const int q    = blockIdx.y * 256 + tid;   // ulonglong2 index within row (0..511)

    ulonglong2 ut[4], w2[16];
    #pragma unroll
    for (int k = 0; k < 4; k++)
        ut[k] = reinterpret_cast<const ulonglong2*>(g_Ut)[k*(DD/4) + q];
    #pragma unroll
    for (int r = 0; r < RFF; r++)
        w2[r] = reinterpret_cast<const ulonglong2*>(W2)[r*(DD/4) + q];

    __shared__ __align__(16) float hs[TRM][20];
    __shared__ __align__(16) ulonglong2 xs[4][256];   // 16 KB x ring

    for (int i = tid; i < TRM*20; i += 256){
        int row = i / 20, j = i % 20;
        hs[row][j] = (j < 4) ? g_h[j*NROWS + row0 + row]
                             : g_g[(size_t)(row0+row)*RFF + (j-4)];
    }

    const ulonglong2* xr = reinterpret_cast<const ulonglong2*>(x) + (size_t)row0*(DD/4) + q;
    ulonglong2*       op = reinterpret_cast<ulonglong2*>(out)     + (size_t)row0*(DD/4) + q;

    // prologue: rows 0..2 in flight (each thread fills only its own slot)
    #pragma unroll
    for (int p = 0; p < 3; p++){
        cp_async16(&xs[p][tid], xr + (size_t)p*(DD/4));
        cp_commit();
    }
    __syncthreads();   // hs table ready

    #pragma unroll
    for (int row = 0; row < TRM; row++){
        if (row + 3 < TRM)
            cp_async16(&xs[(row+3)&3][tid], xr + (size_t)(row+3)*(DD/4));
        cp_commit();                 // empty groups keep the count uniform
        cp_wait3();                  // row's group complete (<=3 newer pending)

        ulonglong2 xa = xs[row & 3][tid];

        float sc[20];
        float4* sc4 = reinterpret_cast<float4*>(sc);
        const float4* hp = reinterpret_cast<const float4*>(&hs[row][0]);
        #pragma unroll
        for (int i = 0; i < 5; i++) sc4[i] = hp[i];

        u64 a0 = xa.x, a1 = xa.y, b0 = 0ull, b1 = 0ull;
        #pragma unroll
        for (int k = 0; k < 4; k++){
            u64 s = pack2(sc[k], sc[k]);
            if (k & 1){ b0 = fma2(s, ut[k].x, b0); b1 = fma2(s, ut[k].y, b1); }
            else      { a0 = fma2(s, ut[k].x, a0); a1 = fma2(s, ut[k].y, a1); }
        }
        #pragma unroll
        for (int r = 0; r < RFF; r++){
            u64 s = pack2(sc[4+r], sc[4+r]);
            if (r & 1){ b0 = fma2(s, w2[r].x, b0); b1 = fma2(s, w2[r].y, b1); }
            else      { a0 = fma2(s, w2[r].x, a0); a1 = fma2(s, w2[r].y, a1); }
        }
        ulonglong2 o;
        o.x = add2(a0, b0);
        o.y = add2(a1, b1);
        op[(size_t)row*(DD/4)] = o;
    }
}

// ======================= launch =======================
extern "C" void kernel_launch(void* const* d_in, const int* in_sizes, int n_in,
                              void* d_out, int out_size){
    const float* x       = (const float*)d_in[0];
    const float* norm_w  = (const float*)d_in[1];
    const float* V       = (const float*)d_in[2];
    const float* U       = (const float*)d_in[3];
    const float* a_logit = (const float*)d_in[4];
    const float* W1      = (const float*)d_in[5];
    const float* W2      = (const float*)d_in[6];
    float* out = (float*)d_out;

    k_prep_a   <<<1, 32>>>(a_logit);                 // launch 0
    k_prep_fold<<<8, 256>>>(norm_w, V, U, W1);       // launch 1
    k_prep_gm  <<<80, 256>>>(norm_w, U, W1);         // launch 2
    k_u        <<<NROWS/TRU, 512>>>(x);              // launch 3  (profiled)
    k_scan     <<<BB*RR, 256>>>();                   // launch 4
    k_post     <<<NROWS/256, 256>>>();               // launch 5
    dim3 gm(NROWS/TRM, 2);
    k_main     <<<gm, 256>>>(x, W2, out);            // launch 6
}

// round 15
// speedup vs baseline: 1.0221x; 1.0086x over previous
#include <cuda_runtime.h>
#include <cstdint>

#define BB 4
#define SS 4096
#define DD 2048
#define RR 4
#define RFF 16
#define NROWS (BB*SS)   // 16384
#define TRU 8           // rows per block in k_u (2 groups x 4 rows)
#define TRM 16          // rows per block in k_main
#define EPS 1e-6f

typedef unsigned long long u64;

// -------- device scratch (no allocation allowed) --------
__device__ __align__(16) float g_ssq[NROWS];
__device__ __align__(16) float g_u  [RR*NROWS];   // planar [r][row], pre-scaled by rmsnorm
__device__ __align__(16) float g_pu [NROWS*RR];   // row-major
__device__ __align__(16) float g_pw1[NROWS*RFF];  // row-major
__device__ __align__(16) float g_h  [RR*NROWS];   // planar [r][row]
__device__ __align__(16) float g_g  [NROWS*RFF];  // row-major
__device__ __align__(16) float g_Vt [RR*DD];      // w*V transposed
__device__ __align__(16) float g_Ut [RR*DD];      // U transposed
__device__ __align__(16) float g_W1t[RFF*DD];     // w*W1 transposed
__device__ float g_G[16];    // U^T U
__device__ float g_M[64];    // U^T (w*W1)
__device__ float g_a[RR];

// -------- packed f32x2 helpers --------
__device__ __forceinline__ u64 fma2(u64 a, u64 b, u64 c){
    u64 d; asm("fma.rn.f32x2 %0, %1, %2, %3;" : "=l"(d) : "l"(a), "l"(b), "l"(c)); return d;
}
__device__ __forceinline__ u64 add2(u64 a, u64 b){
    u64 d; asm("add.rn.f32x2 %0, %1, %2;" : "=l"(d) : "l"(a), "l"(b)); return d;
}
__device__ __forceinline__ u64 pack2(float x, float y){
    u64 r; asm("mov.b64 %0, {%1, %2};" : "=l"(r) : "f"(x), "f"(y)); return r;
}
__device__ __forceinline__ float2 unpack2(u64 p){
    float2 f; asm("mov.b64 {%0, %1}, %2;" : "=f"(f.x), "=f"(f.y) : "l"(p)); return f;
}
__device__ __forceinline__ float warp_sum(float v){
    v += __shfl_down_sync(0xffffffffu, v, 16);
    v += __shfl_down_sync(0xffffffffu, v, 8);
    v += __shfl_down_sync(0xffffffffu, v, 4);
    v += __shfl_down_sync(0xffffffffu, v, 2);
    v += __shfl_down_sync(0xffffffffu, v, 1);
    return v;
}
template<int N>
__device__ __forceinline__ float rs_reduce(float (&v)[N], int lane){
    #pragma unroll
    for (int s = N/2; s >= 1; s >>= 1){
        bool up = (lane & s) != 0;
        #pragma unroll
        for (int i = 0; i < s; i++){
            float send = up ? v[i] : v[i+s];
            float keep = up ? v[i+s] : v[i];
            v[i] = keep + __shfl_xor_sync(0xffffffffu, send, s);
        }
    }
    float r = v[0];
    #pragma unroll
    for (int s = N; s < 32; s <<= 1)
        r += __shfl_xor_sync(0xffffffffu, r, s);
    return r;
}
__device__ __forceinline__ float gelu_tanh(float x){
    float c = 0.7978845608028654f * (x + 0.044715f * x * x * x);
    return 0.5f * x * (1.0f + tanhf(c));
}

// ======================= prep kernels (split for profiler positioning) =======================
__global__ void k_prep_a(const float* __restrict__ a_logit){
    int tid = threadIdx.x;
    if (tid < RR) g_a[tid] = 1.0f / (1.0f + expf(-a_logit[tid]));
}

__global__ void k_prep_fold(const float* __restrict__ norm_w, const float* __restrict__ V,
                            const float* __restrict__ U, const float* __restrict__ W1){
    int d = blockIdx.x * 256 + threadIdx.x;
    float w = norm_w[d];
    #pragma unroll
    for (int r = 0; r < RR; r++){
        g_Vt[r*DD + d] = w * V[d*RR + r];
        g_Ut[r*DD + d] = U[d*RR + r];
    }
    #pragma unroll
    for (int r = 0; r < RFF; r++)
        g_W1t[r*DD + d] = w * W1[d*RFF + r];
}

__global__ void k_prep_gm(const float* __restrict__ norm_w, const float* __restrict__ U,
                          const float* __restrict__ W1){
    int j = blockIdx.x;   // 0..79
    int tid = threadIdx.x;
    float s = 0.f;
    if (j < 16){
        int k = j >> 2, q = j & 3;
        for (int d = tid; d < DD; d += 256)
            s += U[d*RR + k] * U[d*RR + q];
    } else {
        int k = (j-16) >> 4, r = (j-16) & 15;
        for (int d = tid; d < DD; d += 256)
            s += U[d*RR + k] * norm_w[d] * W1[d*RFF + r];
    }
    s = warp_sum(s);
    __shared__ float sh[8];
    if ((tid & 31) == 0) sh[tid >> 5] = s;
    __syncthreads();
    if (tid == 0){
        float t = 0.f;
        #pragma unroll
        for (int i = 0; i < 8; i++) t += sh[i];
        if (j < 16) g_G[j] = t; else g_M[j-16] = t;
    }
}

// ======================= k_u v3: 2-dot weight passes, 64-reg cap, 2 CTA/SM =======================
// 512 threads = 2 groups x 256; group g handles rows rowg..rowg+3; thread owns 8 d's.
// 12 passes x 2 dots. Dots: 0..3=V, 4..7=U, 8..23=W1. Slot = 1+dot (slot 0 = ssq).
__global__ void __launch_bounds__(512, 2) k_u(const float* __restrict__ x){
    const int tid = threadIdx.x;
    const int g   = tid >> 8;
    const int gt  = tid & 255;
    const int w8  = gt >> 5;
    const int l   = gt & 31;
    const int rowg = blockIdx.x * TRU + g*4;

    __shared__ float sred[TRU][25][9];
    __shared__ float tot[TRU][25];

    ulonglong2 xp[4][2];
    #pragma unroll
    for (int i = 0; i < 4; i++){
        const ulonglong2* xr = reinterpret_cast<const ulonglong2*>(x)
                             + (size_t)(rowg+i)*(DD/4) + gt*2;
        xp[i][0] = xr[0];
        xp[i][1] = xr[1];
    }

    #pragma unroll
    for (int pass = 0; pass < 12; pass++){
        const int j0 = 2*pass;
        const int j1 = j0 + 1;
        const float* w0 = (j0 < 4) ? (g_Vt + j0*DD) : (j0 < 8) ? (g_Ut + (j0-4)*DD)
                                                              : (g_W1t + (j0-8)*DD);
        const float* w1 = (j1 < 4) ? (g_Vt + j1*DD) : (j1 < 8) ? (g_Ut + (j1-4)*DD)
                                                              : (g_W1t + (j1-8)*DD);
        ulonglong2 wp[2][2];
        wp[0][0] = reinterpret_cast<const ulonglong2*>(w0)[gt*2];
        wp[0][1] = reinterpret_cast<const ulonglong2*>(w0)[gt*2 + 1];
        wp[1][0] = reinterpret_cast<const ulonglong2*>(w1)[gt*2];
        wp[1][1] = reinterpret_cast<const ulonglong2*>(w1)[gt*2 + 1];

        #pragma unroll
        for (int i = 0; i < 4; i++){
            const int ri = g*4 + i;
            if (pass == 0){
                u64 s = fma2(xp[i][0].x, xp[i][0].x,
                        fma2(xp[i][0].y, xp[i][0].y,
                        fma2(xp[i][1].x, xp[i][1].x,
                        fma2(xp[i][1].y, xp[i][1].y, 0ull))));
                float2 fs = unpack2(s);
                float ss = warp_sum(fs.x + fs.y);
                if (l == 0) sred[ri][0][w8] = ss;
            }
            float p[2];
            #pragma unroll
            for (int j = 0; j < 2; j++){
                u64 a = fma2(xp[i][0].x, wp[j][0].x,
                        fma2(xp[i][0].y, wp[j][0].y,
                        fma2(xp[i][1].x, wp[j][1].x,
                        fma2(xp[i][1].y, wp[j][1].y, 0ull))));
                float2 f = unpack2(a);
                p[j] = f.x + f.y;
            }
            float rv = rs_reduce<2>(p, l);
            if (l < 2) sred[ri][1 + j0 + l][w8] = rv;
        }
        __syncthreads();   // scheduling fence: keep pass register sets disjoint
    }

    if (tid < TRU*25){
        int row = tid / 25, val = tid % 25;
        float s = 0.f;
        #pragma unroll
        for (int ww = 0; ww < 8; ww++) s += sred[row][val][ww];
        tot[row][val] = s;
    }
    __syncthreads();
    if (tid < TRU*25){
        int row = tid / 25, val = tid % 25;
        int gr = blockIdx.x * TRU + row;
        float s = tot[row][val];
        if (val == 0) g_ssq[gr] = s;
        else if (val < 5){
            float scale = rsqrtf(tot[row][0] * (1.0f/DD) + EPS);
            g_u[(val-1)*NROWS + gr] = scale * s;
        }
        else if (val < 9) g_pu[(size_t)gr*RR + (val-5)] = s;
        else              g_pw1[(size_t)gr*RFF + (val-9)] = s;
    }
}

// ======================= k_scan: warp-parallel linear-recurrence scan =======================
__global__ void __launch_bounds__(256) k_scan(){
    const int b = blockIdx.x >> 2;
    const int r = blockIdx.x & 3;
    const float a = g_a[r];
    const int tid = threadIdx.x, l = tid & 31, w = tid >> 5;
    const float* u = g_u + r*NROWS + b*SS;

    float uu[16];
    float4* uu4 = reinterpret_cast<float4*>(uu);
    #pragma unroll
    for (int i = 0; i < 4; i++)
        uu4[i] = reinterpret_cast<const float4*>(u)[tid*4 + i];

    float f = 0.f;
    #pragma unroll
    for (int i = 0; i < 16; i++) f = a*f + uu[i];

    float A = a; A *= A; A *= A; A *= A; A *= A;   // a^16

    float I = f, As = A;
    #pragma unroll
    for (int st = 0; st < 5; st++){
        float gg = __shfl_up_sync(0xffffffffu, I, 1 << st);
        if (l >= (1 << st)) I += As * gg;
        As *= As;
    }

    __shared__ float Tw[8], Ww[8];
    if (l == 31) Tw[w] = I;
    __syncthreads();
    if (tid == 0){
        float A32 = A;
        #pragma unroll
        for (int k = 0; k < 5; k++) A32 *= A32;  // a^512
        float c = 0.f;
        #pragma unroll
        for (int j = 0; j < 8; j++){ Ww[j] = c; c = A32*c + Tw[j]; }
    }
    __syncthreads();

    float Al = 1.f, p = A;
    #pragma unroll
    for (int bit = 0; bit < 5; bit++){ if ((l >> bit) & 1) Al *= p; p *= p; }
    float Iprev = __shfl_up_sync(0xffffffffu, I, 1);
    float c = ((l == 0) ? 0.f : Iprev) + Al * Ww[w];

    float* hh = g_h + r*NROWS + b*SS;
    float h = c;
    float ho[16];
    #pragma unroll
    for (int i = 0; i < 16; i++){ h = a*h + uu[i]; ho[i] = h; }
    float4* ho4 = reinterpret_cast<float4*>(ho);
    #pragma unroll
    for (int i = 0; i < 4; i++)
        reinterpret_cast<float4*>(hh)[tid*4 + i] = ho4[i];
}

// ======================= k_post: per-row scale1, t, gelu (R12 exact) =======================
__global__ void __launch_bounds__(256) k_post(){
    __shared__ float sG[16], sM[64];
    int tid = threadIdx.x;
    if (tid < 16) sG[tid] = g_G[tid];
    if (tid < 64) sM[tid] = g_M[tid];
    __syncthreads();

    int row = blockIdx.x * 256 + tid;
    float h[4], p[4];
    #pragma unroll
    for (int k = 0; k < 4; k++) h[k] = g_h[k*NROWS + row];
    float4 p4 = reinterpret_cast<const float4*>(g_pu)[row];
    p[0]=p4.x; p[1]=p4.y; p[2]=p4.z; p[3]=p4.w;

    float s1 = g_ssq[row];
    #pragma unroll
    for (int k = 0; k < 4; k++) s1 += 2.0f * h[k] * p[k];
    #pragma unroll
    for (int k = 0; k < 4; k++)
        #pragma unroll
        for (int q = 0; q < 4; q++) s1 += h[k] * h[q] * sG[k*4+q];
    float scale = rsqrtf(s1 * (1.0f/DD) + EPS);

    #pragma unroll
    for (int r = 0; r < RFF; r++){
        float t = g_pw1[(size_t)row*RFF + r];
        #pragma unroll
        for (int k = 0; k < 4; k++) t += h[k] * sM[k*16 + r];
        g_g[(size_t)row*RFF + r] = gelu_tanh(t * scale);
    }
}

// ======================= k_main: out = x + U h + g @ W2 (R12 exact) =======================
__global__ void __launch_bounds__(256, 2) k_main(const float* __restrict__ x,
                                                 const float* __restrict__ W2,
                                                 float* __restrict__ out){
    const int row0 = blockIdx.x * TRM;
    const int tid  = threadIdx.x;
    const int q    = blockIdx.y * 256 + tid;

    ulonglong2 ut[4], w2[16];
    #pragma unroll
    for (int k = 0; k < 4; k++)
        ut[k] = reinterpret_cast<const ulonglong2*>(g_Ut)[k*(DD/4) + q];
    #pragma unroll
    for (int r = 0; r < RFF; r++)
        w2[r] = reinterpret_cast<const ulonglong2*>(W2)[r*(DD/4) + q];

    __shared__ __align__(16) float hs[TRM][20];
    for (int i = tid; i < TRM*20; i += 256){
        int row = i / 20, j = i % 20;
        hs[row][j] = (j < 4) ? g_h[j*NROWS + row0 + row]
                             : g_g[(size_t)(row0+row)*RFF + (j-4)];
    }
    __syncthreads();

    const ulonglong2* xr = reinterpret_cast<const ulonglong2*>(x) + (size_t)row0*(DD/4) + q;
    ulonglong2*       op = reinterpret_cast<ulonglong2*>(out)     + (size_t)row0*(DD/4) + q;

    ulonglong2 xa = xr[0];
    #pragma unroll
    for (int row = 0; row < TRM; row++){
        ulonglong2 xn = xa;
        if (row + 1 < TRM) xn = xr[(size_t)(row+1)*(DD/4)];

        float sc[20];
        float4* sc4 = reinterpret_cast<float4*>(sc);
        const float4* hp = reinterpret_cast<const float4*>(&hs[row][0]);
        #pragma unroll
        for (int i = 0; i < 5; i++) sc4[i] = hp[i];

        u64 a0 = xa.x, a1 = xa.y, b0 = 0ull, b1 = 0ull;
        #pragma unroll
        for (int k = 0; k < 4; k++){
            u64 s = pack2(sc[k], sc[k]);
            if (k & 1){ b0 = fma2(s, ut[k].x, b0); b1 = fma2(s, ut[k].y, b1); }
            else      { a0 = fma2(s, ut[k].x, a0); a1 = fma2(s, ut[k].y, a1); }
        }
        #pragma unroll
        for (int r = 0; r < RFF; r++){
            u64 s = pack2(sc[4+r], sc[4+r]);
            if (r & 1){ b0 = fma2(s, w2[r].x, b0); b1 = fma2(s, w2[r].y, b1); }
            else      { a0 = fma2(s, w2[r].x, a0); a1 = fma2(s, w2[r].y, a1); }
        }
        ulonglong2 o;
        o.x = add2(a0, b0);
        o.y = add2(a1, b1);
        op[(size_t)row*(DD/4)] = o;
        xa = xn;
    }
}

// ======================= launch =======================
extern "C" void kernel_launch(void* const* d_in, const int* in_sizes, int n_in,
                              void* d_out, int out_size){
    const float* x       = (const float*)d_in[0];
    const float* norm_w  = (const float*)d_in[1];
    const float* V       = (const float*)d_in[2];
    const float* U       = (const float*)d_in[3];
    const float* a_logit = (const float*)d_in[4];
    const float* W1      = (const float*)d_in[5];
    const float* W2      = (const float*)d_in[6];
    float* out = (float*)d_out;

    k_prep_a   <<<1, 32>>>(a_logit);                 // launch 0
    k_prep_fold<<<8, 256>>>(norm_w, V, U, W1);       // launch 1
    k_prep_gm  <<<80, 256>>>(norm_w, U, W1);         // launch 2
    k_u        <<<NROWS/TRU, 512>>>(x);              // launch 3  (profiled)
    k_scan     <<<BB*RR, 256>>>();                   // launch 4
    k_post     <<<NROWS/256, 256>>>();               // launch 5
    dim3 gm(NROWS/TRM, 2);
    k_main     <<<gm, 256>>>(x, W2, out);            // launch 6
}